// round 2
// baseline (speedup 1.0000x reference)
#include <cuda_runtime.h>

// HSTU positional encoder:
// out[i, :] = x[i,:]*sqrt(D) + pos_weight[pos_ind(i), :] + ts_weight[ts_ind(i), :]
// D = 512, L = 32768, B = 16, P = 8192, NTB = 2048.

#define D 512
#define ALPHA 22.627416997969522f   // sqrt(512)
#define MAX_POS 8192
#define NTB 2048
#define TIME_BUCKET_INCREMENTS 60.0f

__global__ __launch_bounds__(128)
void hstu_pos_enc_kernel(
    const int* __restrict__ seq_lengths,   // [B]
    const int* __restrict__ seq_offsets,   // [B+1]
    const float* __restrict__ x,           // [L, D]
    const int* __restrict__ num_targets,   // [B]
    const int* __restrict__ seq_ts,        // [L]
    const float* __restrict__ pos_weight,  // [P, D]
    const float* __restrict__ ts_weight,   // [NTB+1, D]
    float* __restrict__ out,               // [L, D]
    int B, int L)
{
    const int row = blockIdx.x;
    if (row >= L) return;

    // Per-warp index computation on lane 0, broadcast via shfl (no CTA barrier).
    int pos_ind, ts_ind;
    if ((threadIdx.x & 31) == 0) {
        // --- find batch b: seq_offsets[b] <= row < seq_offsets[b+1] ---
        int lo = 0, hi = B - 1;
        while (lo < hi) {
            int mid = (lo + hi + 1) >> 1;
            if (seq_offsets[mid] <= row) lo = mid; else hi = mid - 1;
        }
        const int b = lo;

        const int off = seq_offsets[b];
        const int rel_pos = row - off;

        // --- positional index ---
        int len = seq_lengths[b]; if (len < 0) len = 0;
        int nt  = num_targets[b]; if (nt  < 0) nt  = 0;
        int high_ind = len - nt;  if (high_ind < 0) high_ind = 0;

        int p = (rel_pos < high_ind) ? rel_pos : high_ind;
        p = high_ind - p;                       // MAX_CONTEXTUAL_SEQ_LEN = 0
        if (p > MAX_POS - 1) p = MAX_POS - 1;
        if (p < 0) p = 0;
        pos_ind = p;

        // --- time-bucket index ---
        const int end = seq_offsets[b + 1];
        const float qt = (float)seq_ts[end - 1];
        const float tt = (float)seq_ts[row];
        float dt = qt - tt;                     // TIME_DELTA = 0
        if (dt < 1e-6f) dt = 1e-6f;
        dt = dt / TIME_BUCKET_INCREMENTS;
        const float v = sqrtf(dt);              // TIME_BUCKET_SCALE = 1
        int t = (int)v;                         // trunc, v >= 0
        if (t > NTB) t = NTB;
        ts_ind = t;
    }
    pos_ind = __shfl_sync(0xFFFFFFFFu, pos_ind, 0);
    ts_ind  = __shfl_sync(0xFFFFFFFFu, ts_ind, 0);

    // 128 threads x float4 = 512 floats per row
    const float4* __restrict__ xr = (const float4*)(x          + (size_t)row     * D);
    const float4* __restrict__ pr = (const float4*)(pos_weight + (size_t)pos_ind * D);
    const float4* __restrict__ tr = (const float4*)(ts_weight  + (size_t)ts_ind  * D);
    float4* __restrict__       orow = (float4*)(out + (size_t)row * D);

    const int t = threadIdx.x;
    float4 xv = xr[t];
    float4 pv = pr[t];
    float4 tv = tr[t];
    float4 ov;
    ov.x = fmaf(xv.x, ALPHA, pv.x + tv.x);
    ov.y = fmaf(xv.y, ALPHA, pv.y + tv.y);
    ov.z = fmaf(xv.z, ALPHA, pv.z + tv.z);
    ov.w = fmaf(xv.w, ALPHA, pv.w + tv.w);
    orow[t] = ov;
}

extern "C" void kernel_launch(void* const* d_in, const int* in_sizes, int n_in,
                              void* d_out, int out_size)
{
    // Input order (metadata): [max_seq_len?], seq_lengths, seq_offsets,
    // seq_embeddings, num_targets, seq_timestamps, pos_weight, ts_weight.
    // Handle both with and without the leading python-int scalar.
    int o = (n_in == 8) ? 1 : 0;

    const int*   seq_lengths = (const int*)  d_in[o + 0];
    const int*   seq_offsets = (const int*)  d_in[o + 1];
    const float* x           = (const float*)d_in[o + 2];
    const int*   num_targets = (const int*)  d_in[o + 3];
    const int*   seq_ts      = (const int*)  d_in[o + 4];
    const float* pos_weight  = (const float*)d_in[o + 5];
    const float* ts_weight   = (const float*)d_in[o + 6];
    float*       out         = (float*)d_out;

    const int B = in_sizes[o + 0];          // seq_lengths element count
    const int L = out_size / D;             // total token rows

    hstu_pos_enc_kernel<<<L, 128>>>(seq_lengths, seq_offsets, x, num_targets,
                                    seq_ts, pos_weight, ts_weight, out, B, L);
}

// round 3
// speedup vs baseline: 1.3081x; 1.3081x over previous
#include <cuda_runtime.h>

// HSTU positional encoder:
// out[i, :] = x[i,:]*sqrt(D) + pos_weight[pos_ind(i), :] + ts_weight[ts_ind(i), :]
// D = 512, L = 32768, B = 16, P = 8192, NTB = 2048.

#define D 512
#define ALPHA 22.627416997969522f   // sqrt(512)
#define MAX_POS 8192
#define NTB 2048
#define TIME_BUCKET_INCREMENTS 60.0f
#define R 4                          // rows per CTA

__global__ __launch_bounds__(128)
void hstu_pos_enc_kernel(
    const int* __restrict__ seq_lengths,   // [B]
    const int* __restrict__ seq_offsets,   // [B+1]
    const float* __restrict__ x,           // [L, D]
    const int* __restrict__ num_targets,   // [B]
    const int* __restrict__ seq_ts,        // [L]
    const float* __restrict__ pos_weight,  // [P, D]
    const float* __restrict__ ts_weight,   // [NTB+1, D]
    float* __restrict__ out,               // [L, D]
    int B, int L)
{
    const int base = blockIdx.x * R;
    const int lane = threadIdx.x & 31;

    // Lanes 0..R-1 each compute the index pair for row base+lane.
    int pos_i = 0, ts_i = 0;
    if (lane < R && base + lane < L) {
        const int row = base + lane;

        // --- find batch b: seq_offsets[b] <= row < seq_offsets[b+1] ---
        int lo = 0, hi = B - 1;
        while (lo < hi) {
            int mid = (lo + hi + 1) >> 1;
            if (seq_offsets[mid] <= row) lo = mid; else hi = mid - 1;
        }
        const int b = lo;

        const int off = seq_offsets[b];
        const int rel_pos = row - off;

        // --- positional index ---
        int len = seq_lengths[b]; if (len < 0) len = 0;
        int nt  = num_targets[b]; if (nt  < 0) nt  = 0;
        int high_ind = len - nt;  if (high_ind < 0) high_ind = 0;

        int p = (rel_pos < high_ind) ? rel_pos : high_ind;
        p = high_ind - p;                       // MAX_CONTEXTUAL_SEQ_LEN = 0
        if (p > MAX_POS - 1) p = MAX_POS - 1;
        if (p < 0) p = 0;
        pos_i = p;

        // --- time-bucket index ---
        const int end = seq_offsets[b + 1];
        const float qt = (float)seq_ts[end - 1];
        const float tt = (float)seq_ts[row];
        float dt = qt - tt;                     // TIME_DELTA = 0
        if (dt < 1e-6f) dt = 1e-6f;
        dt = dt / TIME_BUCKET_INCREMENTS;
        const float v = sqrtf(dt);              // TIME_BUCKET_SCALE = 1
        int ti = (int)v;                        // trunc, v >= 0
        if (ti > NTB) ti = NTB;
        ts_i = ti;
    }

    int pos_ind[R], ts_ind[R];
    #pragma unroll
    for (int r = 0; r < R; r++) {
        pos_ind[r] = __shfl_sync(0xFFFFFFFFu, pos_i, r);
        ts_ind[r]  = __shfl_sync(0xFFFFFFFFu, ts_i,  r);
    }

    const int t = threadIdx.x;

    // Batch all loads up front: 12 independent LDG.128 per thread.
    // x is stream-once -> evict-first (.cs); tables are reused -> default cached.
    float4 xv[R], pv[R], tv[R];
    #pragma unroll
    for (int r = 0; r < R; r++) {
        const int row = base + r;
        xv[r] = __ldcs((const float4*)(x + (size_t)row * D) + t);
        pv[r] = *((const float4*)(pos_weight + (size_t)pos_ind[r] * D) + t);
        tv[r] = *((const float4*)(ts_weight  + (size_t)ts_ind[r]  * D) + t);
    }

    #pragma unroll
    for (int r = 0; r < R; r++) {
        const int row = base + r;
        float4 ov;
        ov.x = fmaf(xv[r].x, ALPHA, pv[r].x + tv[r].x);
        ov.y = fmaf(xv[r].y, ALPHA, pv[r].y + tv[r].y);
        ov.z = fmaf(xv[r].z, ALPHA, pv[r].z + tv[r].z);
        ov.w = fmaf(xv[r].w, ALPHA, pv[r].w + tv[r].w);
        __stcs((float4*)(out + (size_t)row * D) + t, ov);   // stream-once store
    }
}

extern "C" void kernel_launch(void* const* d_in, const int* in_sizes, int n_in,
                              void* d_out, int out_size)
{
    // Input order (metadata): [max_seq_len?], seq_lengths, seq_offsets,
    // seq_embeddings, num_targets, seq_timestamps, pos_weight, ts_weight.
    int o = (n_in == 8) ? 1 : 0;

    const int*   seq_lengths = (const int*)  d_in[o + 0];
    const int*   seq_offsets = (const int*)  d_in[o + 1];
    const float* x           = (const float*)d_in[o + 2];
    const int*   num_targets = (const int*)  d_in[o + 3];
    const int*   seq_ts      = (const int*)  d_in[o + 4];
    const float* pos_weight  = (const float*)d_in[o + 5];
    const float* ts_weight   = (const float*)d_in[o + 6];
    float*       out         = (float*)d_out;

    const int B = in_sizes[o + 0];          // seq_lengths element count
    const int L = out_size / D;             // total token rows

    const int grid = (L + R - 1) / R;
    hstu_pos_enc_kernel<<<grid, 128>>>(seq_lengths, seq_offsets, x, num_targets,
                                       seq_ts, pos_weight, ts_weight, out, B, L);
}